// round 1
// baseline (speedup 1.0000x reference)
#include <cuda_runtime.h>

// SegmentPhysicsModel: per-sample single-diode Newton solve for 4 solar panels.
// Key optimization: X_POS/X_NEG (identical configs) and Y_POS/Y_NEG are
// mutually exclusive by the sign of sun_x / sun_y (the dark panel's current is
// clamped to 0), so we do 3 sign-selected Newton solves instead of 6.
// The three solves are interleaved in one unrolled loop for ILP across the
// MUFU (exp) dependency chains.

#define JSC        170.0f
#define ALPHA_ISC  0.0006f
#define T_REFC     298.15f
#define RS_CELL    0.01f
#define INV_RSH    (1.0f/500.0f)
#define INV_GREF   (1.0f/1366.0f)
#define SOLAR_C    1366.0f
#define SUN_DIST   149600000.0f
#define NKB        (2.5f * 8.617333262e-05f)   // N_IDEAL * KB_Q
// VOC_CELL / vt_ref computed in double, folded to float:
#define VOC_OVER_VTREF ((float)(2.35 / (2.5 * 8.617333262e-05 * 298.15)))

#define AREA1 (0.0604f * 0.0398f)   // large cells
#define AREA2 (0.0403f * 0.0306f)   // small cells

__device__ __forceinline__ void newton_step(float& I, float v_cell, float iph,
                                            float i0, float inv_vt, float ecoef) {
    float u  = fmaf(I, RS_CELL, v_cell);
    float z  = fminf(fmaxf(u * inv_vt, -40.0f), 40.0f);
    float e  = __expf(z);
    float f  = iph - i0 * (e - 1.0f) - u * INV_RSH - I;
    float fp = fmaf(-ecoef, e, -(RS_CELL * INV_RSH) - 1.0f);
    I = I - __fdividef(f, fp);
}

__global__ void __launch_bounds__(256)
segment_physics_kernel(const float* __restrict__ x,
                       const float* __restrict__ f_xn,
                       const float* __restrict__ f_yn,
                       const float* __restrict__ f_xp,
                       const float* __restrict__ f_yp,
                       float* __restrict__ out, int n) {
    int i = blockIdx.x * blockDim.x + threadIdx.x;
    if (i >= n) return;

    const float* p = x + (size_t)i * 11;
    float sx   = p[0];
    float sy   = p[1];
    float tpx  = p[2];
    float tnx  = p[3];
    float tpy  = p[4];
    float tny  = p[5];
    float V    = p[6];
    float dist = p[7];

    float r   = SUN_DIST / dist;
    float irr = SOLAR_C * r * r;

    // Sign-based selection (dark side contributes exactly 0 after max(I,0))
    bool  xp = sx > 0.0f;
    float Gx = irr * fabsf(sx);
    float Tx = xp ? tpx : tnx;
    float fx = xp ? f_xp[0] : f_xn[0];

    bool  yp = sy > 0.0f;
    float Gy = irr * fabsf(sy);
    float Ty = yp ? tpy : tny;
    float fy = yp ? f_yp[0] : f_yn[0];
    float areaY = yp ? AREA2 : AREA1;
    float parY  = yp ? 10.0f : 6.0f;   // 180/18 vs 108/18

    float v_cell  = V * (1.0f / 18.0f);
    float inv_em1 = 1.0f / expm1f(VOC_OVER_VTREF);

    // Solve 1: X config A (area1, parallel=2). Solve 2: X config B (area2, parallel=7).
    // Solve 3: Y selected config.
    float gx_n = Gx * INV_GREF;
    float tx_c = 1.0f + ALPHA_ISC * (Tx - T_REFC);
    float gy_n = Gy * INV_GREF;
    float ty_c = 1.0f + ALPHA_ISC * (Ty - T_REFC);

    float inv_vtx = 1.0f / (NKB * Tx);
    float inv_vty = 1.0f / (NKB * Ty);

    float iph1 = JSC * AREA1 * gx_n * tx_c;
    float iph2 = JSC * AREA2 * gx_n * tx_c;
    float iph3 = JSC * areaY * gy_n * ty_c;

    float i0_1 = JSC * AREA1 * inv_em1;
    float i0_2 = JSC * AREA2 * inv_em1;
    float i0_3 = JSC * areaY * inv_em1;

    float ec1 = i0_1 * RS_CELL * inv_vtx;
    float ec2 = i0_2 * RS_CELL * inv_vtx;
    float ec3 = i0_3 * RS_CELL * inv_vty;

    float I1 = iph1, I2 = iph2, I3 = iph3;

    #pragma unroll
    for (int it = 0; it < 25; ++it) {
        newton_step(I1, v_cell, iph1, i0_1, inv_vtx, ec1);
        newton_step(I2, v_cell, iph2, i0_2, inv_vtx, ec2);
        newton_step(I3, v_cell, iph3, i0_3, inv_vty, ec3);
    }

    float ix = fx * (2.0f * fmaxf(I1, 0.0f) + 7.0f * fmaxf(I2, 0.0f));
    float iy = fy * parY * fmaxf(I3, 0.0f);
    out[i] = 0.92f * (ix + iy);
}

extern "C" void kernel_launch(void* const* d_in, const int* in_sizes, int n_in,
                              void* d_out, int out_size) {
    const float* x    = (const float*)d_in[0];
    const float* f_xn = (const float*)d_in[1];
    const float* f_yn = (const float*)d_in[2];
    const float* f_xp = (const float*)d_in[3];
    const float* f_yp = (const float*)d_in[4];
    float* out = (float*)d_out;

    int n = in_sizes[0] / 11;
    int threads = 256;
    int blocks = (n + threads - 1) / threads;
    segment_physics_kernel<<<blocks, threads>>>(x, f_xn, f_yn, f_xp, f_yp, out, n);
}

// round 2
// speedup vs baseline: 1.9710x; 1.9710x over previous
#include <cuda_runtime.h>

// SegmentPhysicsModel — 3 sign-selected single-diode solves per sample.
//
// R2 changes vs R1 (13.1us):
//  * 25 -> 5 fixed-point iterations. In the input range (z = u/vt in [19.2, 31.1])
//    the residual is linear in I to within ~3e-4, so the iteration is a
//    contraction with factor <= ~1.4e-4/step; 5 steps is f32-exact with margin.
//    The fixed point (f = 0) is identical to the reference's 25-iter Newton.
//  * Division-free update: fp is constant to within 2.8e-4, so use
//    I += f * (1/1.00016). Fixed point unchanged (any fp gives f=0).
//  * exp via raw ex2.approx with inv_vt*log2e prefolded; expm1f(36.586) -> ex2
//    of a compile-time constant (exp >> 1).
//  * Clamp dropped (never binds for the given input ranges).
//  * Inputs staged through shared memory (stride-11 per-thread reads are
//    uncoalesced from GMEM).

#define TPB        256
#define NFEAT      11

#define JSC        170.0
#define ALPHA_ISC  0.0006f
#define T_REFC     298.15f
#define RS         0.01f
#define INV_RSH    0.002f              // 1/500
#define INV_GREF   (1.0f/1366.0f)
#define SOLAR_C    1366.0f
#define SUN_DIST   149600000.0f
#define NKB        (2.5f * 8.617333262e-05f)
#define LOG2E      1.4426950408889634

#define VT_REF_D   (2.5 * 8.617333262e-05 * 298.15)
// ex2 argument for 1/expm1(Voc/vt_ref):  exp(x) - 1 == exp(x) to f32 for x~36.6
#define INV_EM1_ARG ((float)(-(2.35 / VT_REF_D) * LOG2E))

#define C_A1       ((float)(JSC * 0.0604 * 0.0398))   // JSC * area_large
#define C_A2       ((float)(JSC * 0.0403 * 0.0306))   // JSC * area_small

#define STEP       0.99984f            // ~ -1/fp
#define NITER      5

__device__ __forceinline__ float ex2f(float z) {
    float r;
    asm("ex2.approx.f32 %0, %1;" : "=f"(r) : "f"(z));
    return r;
}

// One fixed-point step: I += STEP * (iph - i0*(e^z - 1) - u/Rsh - I)
// c0 = iph + i0 prefolded; k = inv_vt * log2(e).
__device__ __forceinline__ void fp_step(float& I, float v_cell, float c0,
                                        float i0, float k) {
    float u = fmaf(I, RS, v_cell);
    float e = ex2f(u * k);
    float t = fmaf(-i0, e, c0);
    t = fmaf(-INV_RSH, u, t);
    float f = t - I;
    I = fmaf(STEP, f, I);
}

__global__ void __launch_bounds__(TPB)
segment_physics_kernel(const float* __restrict__ x,
                       const float* __restrict__ f_xn,
                       const float* __restrict__ f_yn,
                       const float* __restrict__ f_xp,
                       const float* __restrict__ f_yp,
                       float* __restrict__ out, int n) {
    __shared__ float s[TPB * NFEAT];

    int i = blockIdx.x * TPB + threadIdx.x;
    int base = blockIdx.x * TPB * NFEAT;
    int total = n * NFEAT;

    #pragma unroll
    for (int j = 0; j < NFEAT; ++j) {
        int idx = j * TPB + threadIdx.x;
        int g = base + idx;
        if (g < total) s[idx] = x[g];
    }
    __syncthreads();

    if (i >= n) return;

    const float* p = s + threadIdx.x * NFEAT;
    float sx   = p[0];
    float sy   = p[1];
    float tpx  = p[2];
    float tnx  = p[3];
    float tpy  = p[4];
    float tny  = p[5];
    float V    = p[6];
    float dist = p[7];

    float r   = SUN_DIST / dist;
    float irr = SOLAR_C * r * r;

    // Dark-side panel's root is negative -> clamps to 0; select the lit side.
    bool  xp = sx > 0.0f;
    float Gx = irr * fabsf(sx);
    float Tx = xp ? tpx : tnx;
    float fx = xp ? f_xp[0] : f_xn[0];

    bool  yp = sy > 0.0f;
    float Gy = irr * fabsf(sy);
    float Ty = yp ? tpy : tny;
    float fy = yp ? f_yp[0] : f_yn[0];
    float cAY  = yp ? C_A2 : C_A1;     // y_pos: small cells, y_neg: large cells
    float parY = yp ? 10.0f : 6.0f;    // 180/18 vs 108/18

    float v_cell  = V * (1.0f / 18.0f);
    float inv_em1 = ex2f(INV_EM1_ARG);

    float gtx = (Gx * INV_GREF) * fmaf(ALPHA_ISC, Tx - T_REFC, 1.0f);
    float gty = (Gy * INV_GREF) * fmaf(ALPHA_ISC, Ty - T_REFC, 1.0f);

    float kx = (float)LOG2E / (NKB * Tx);
    float ky = (float)LOG2E / (NKB * Ty);

    float iph1 = C_A1 * gtx;           // X large cells  (parallel = 36/18 = 2)
    float iph2 = C_A2 * gtx;           // X small cells  (parallel = 126/18 = 7)
    float iph3 = cAY  * gty;           // Y selected config

    float i0_1 = C_A1 * inv_em1;
    float i0_2 = C_A2 * inv_em1;
    float i0_3 = cAY  * inv_em1;

    float c0_1 = iph1 + i0_1;
    float c0_2 = iph2 + i0_2;
    float c0_3 = iph3 + i0_3;

    float I1 = iph1, I2 = iph2, I3 = iph3;

    #pragma unroll
    for (int it = 0; it < NITER; ++it) {
        fp_step(I1, v_cell, c0_1, i0_1, kx);
        fp_step(I2, v_cell, c0_2, i0_2, kx);
        fp_step(I3, v_cell, c0_3, i0_3, ky);
    }

    float ix = fx * fmaf(2.0f, fmaxf(I1, 0.0f), 7.0f * fmaxf(I2, 0.0f));
    float iy = fy * parY * fmaxf(I3, 0.0f);
    out[i] = 0.92f * (ix + iy);
}

extern "C" void kernel_launch(void* const* d_in, const int* in_sizes, int n_in,
                              void* d_out, int out_size) {
    const float* x    = (const float*)d_in[0];
    const float* f_xn = (const float*)d_in[1];
    const float* f_yn = (const float*)d_in[2];
    const float* f_xp = (const float*)d_in[3];
    const float* f_yp = (const float*)d_in[4];
    float* out = (float*)d_out;

    int n = in_sizes[0] / NFEAT;
    int blocks = (n + TPB - 1) / TPB;
    segment_physics_kernel<<<blocks, TPB>>>(x, f_xn, f_yn, f_xp, f_yp, out, n);
}